// round 13
// baseline (speedup 1.0000x reference)
#include <cuda_runtime.h>
#include <cuda_fp16.h>
#include <math.h>
#include <cstdint>

#define H 32
#define DM 4096
#define DK 128
#define SQ 1024
#define LTOT 4096
#define MAXSEQ 8192
#define RSQRT_DK 0.08838834764831845f

// GEMM tiling: CTA 128x128, warp tile 64x32 (2x4 warps), BK=32, 3 stages, 2 CTAs/SM
// smem rows: 64B (32 fp16) with XOR swizzle (group ^= (row>>1)&3)
#define STAGES 3
#define BKT 32
#define ROWB 64
#define MATB (128 * ROWB)            // 8192 B per matrix tile (128 rows x 32 k)

// ============================ scratch (device globals) ============================
__device__ __align__(16) __half g_X[(size_t)SQ * DM];
__device__ __align__(16) __half g_Wqt[(size_t)H * DK * DM];
__device__ __align__(16) __half g_K[(size_t)H * LTOT * DK];
__device__ __align__(16) __half g_Q[(size_t)H * SQ * DK];
__device__ __align__(16) __half g_P[(size_t)H * SQ * LTOT];
__device__ __align__(16) __half g_Vt[(size_t)H * DK * LTOT];
__device__ __align__(16) __half g_C[(size_t)SQ * DM];
__device__ __align__(16) __half g_Wot[(size_t)DM * DM];
__device__ float g_sum[H * LTOT];
__device__ float g_kn[H * DK], g_vn[H * DK];

// ============================ helpers ============================
__device__ __forceinline__ uint32_t smem_to_u32(const void* p) {
    uint32_t a;
    asm("{ .reg .u64 t; cvta.to.shared.u64 t, %1; cvt.u32.u64 %0, t; }" : "=r"(a) : "l"(p));
    return a;
}

__device__ __forceinline__ void ldm_x4(uint32_t (&r)[4], uint32_t addr) {
    asm volatile("ldmatrix.sync.aligned.m8n8.x4.shared.b16 {%0,%1,%2,%3}, [%4];"
                 : "=r"(r[0]), "=r"(r[1]), "=r"(r[2]), "=r"(r[3]) : "r"(addr));
}

__device__ __forceinline__ void mma16816(float (&d)[4], const uint32_t (&a)[4],
                                         uint32_t b0, uint32_t b1) {
    asm volatile(
        "mma.sync.aligned.m16n8k16.row.col.f32.f16.f16.f32 "
        "{%0,%1,%2,%3}, {%4,%5,%6,%7}, {%8,%9}, {%0,%1,%2,%3};"
        : "+f"(d[0]), "+f"(d[1]), "+f"(d[2]), "+f"(d[3])
        : "r"(a[0]), "r"(a[1]), "r"(a[2]), "r"(a[3]), "r"(b0), "r"(b1));
}

__device__ __forceinline__ void cp16(uint32_t s, const void* g) {
    asm volatile("cp.async.ca.shared.global [%0], [%1], 16;" :: "r"(s), "l"(g));
}
#define CP_COMMIT() asm volatile("cp.async.commit_group;" ::: "memory")
#define CP_WAIT1()  asm volatile("cp.async.wait_group 1;" ::: "memory")

// ============================ GEMM mainloop (1-term fp16) ============================
// acc[4][4][4] += sum over K of A[m][k] * B[n][k]. CTA 128x128, warp tile 64x32.
__device__ __forceinline__ void gemm_main(
    const __half* __restrict__ A0, const __half* __restrict__ B0,
    int lda, int ldb, int ktiles, char* sm, float (&acc)[4][4][4])
{
    constexpr int STAGEB = 2 * MATB;
    const int tid = threadIdx.x;
    const int wid = tid >> 5, lane = tid & 31;
    const int wm = wid >> 2, wn = wid & 3;
    uint32_t smb = smem_to_u32(sm);

#pragma unroll
    for (int mf = 0; mf < 4; mf++)
#pragma unroll
        for (int nf = 0; nf < 4; nf++)
#pragma unroll
            for (int i = 0; i < 4; i++) acc[mf][nf][i] = 0.f;

    auto load_stage = [&](int slot, int c) {
#pragma unroll
        for (int j = 0; j < 4; j++) {
            int i = tid + j * 256;
            int mat = i >> 9;
            int rem = i & 511;
            int row = rem >> 2, c4 = rem & 3;
            const __half* src = mat ? B0 : A0;
            int ld = mat ? ldb : lda;
            const void* g = src + (size_t)row * ld + (size_t)c * BKT + c4 * 8;
            uint32_t sw = (uint32_t)(c4 ^ ((row >> 1) & 3));
            uint32_t s = smb + slot * STAGEB + mat * MATB + row * ROWB + sw * 16;
            cp16(s, g);
        }
        CP_COMMIT();
    };

    const uint32_t lrow = (uint32_t)(lane & 15);
    const uint32_t lchunk = (uint32_t)((lane >> 4) & 1);
    const uint32_t arowi = (uint32_t)(wm * 64) + lrow;
    const uint32_t browi = (uint32_t)(wn * 32) + lrow;

    auto compute = [&](int slot) {
        uint32_t base = smb + slot * STAGEB;
#pragma unroll
        for (int ks = 0; ks < 2; ks++) {
            uint32_t chunk = (uint32_t)ks * 2 + lchunk;
            uint32_t fa[4][4], fb[2][4];
#pragma unroll
            for (int mf = 0; mf < 4; mf++) {
                uint32_t row = arowi + mf * 16;
                uint32_t a = base + row * ROWB + ((chunk ^ ((row >> 1) & 3)) << 4);
                ldm_x4(fa[mf], a);
            }
#pragma unroll
            for (int nb = 0; nb < 2; nb++) {
                uint32_t row = browi + nb * 16;
                uint32_t b = base + MATB + row * ROWB + ((chunk ^ ((row >> 1) & 3)) << 4);
                ldm_x4(fb[nb], b);
            }
#pragma unroll
            for (int mf = 0; mf < 4; mf++)
#pragma unroll
                for (int nf = 0; nf < 4; nf++) {
                    int nb = nf >> 1, sel = nf & 1;
                    mma16816(acc[mf][nf], fa[mf], fb[nb][sel], fb[nb][2 + sel]);
                }
        }
    };

    load_stage(0, 0);
    if (ktiles > 1) load_stage(1, 1);
    else CP_COMMIT();
#pragma unroll 1
    for (int c = 0; c < ktiles; c++) {
        CP_WAIT1();
        __syncthreads();
        if (c + 2 < ktiles) load_stage((c + 2) % 3, c + 2);
        else CP_COMMIT();
        compute(c % 3);
    }
}

#define EPI_COORDS() \
    const int tid = threadIdx.x; \
    const int wid = tid >> 5, lane = tid & 31; \
    const int wm = wid >> 2, wn = wid & 3; \
    const int g = lane >> 2, t2 = (lane & 3) * 2;

// ============================ GEMM kernels ============================
// qproj: X single x Wq single -> Q single
__global__ void __launch_bounds__(256, 2) k_qproj(const float* __restrict__ bq) {
    extern __shared__ char sm[];
    int h = blockIdx.x, mt = blockIdx.y;
    float acc[4][4][4];
    gemm_main(g_X + (size_t)mt * 128 * DM, g_Wqt + (size_t)h * DK * DM,
              DM, DM, DM / BKT, sm, acc);
    EPI_COORDS();
    const float* bqp = bq + h * DK;
    size_t rb = (size_t)h * SQ + (size_t)mt * 128;
#pragma unroll
    for (int mf = 0; mf < 4; mf++)
#pragma unroll
        for (int nf = 0; nf < 4; nf++) {
            int col = wn * 32 + nf * 8 + t2;
            float b0 = bqp[col], b1 = bqp[col + 1];
            int r0 = wm * 64 + mf * 16 + g;
#pragma unroll
            for (int half = 0; half < 2; half++) {
                int r = r0 + half * 8;
                __half h0 = __float2half(acc[mf][nf][half * 2 + 0] + b0);
                __half h1 = __float2half(acc[mf][nf][half * 2 + 1] + b1);
                size_t o = (rb + r) * DK + col;
                *(__half2*)&g_Q[o] = __halves2half2(h0, h1);
            }
        }
}

// ======================= scores: persistent-Q streaming kernel =======================
#define SC_A_BYTES 32768                      // Q single: 4 chunk-blocks x MATB
#define SC_BSTAGE  8192                       // K single: 1 mat x MATB
#define SC_SMEM (SC_A_BYTES + 3 * SC_BSTAGE)  // 57344

__global__ void __launch_bounds__(256, 2) k_scores() {
    extern __shared__ char sm[];
    const int tid = threadIdx.x;
    const int wid = tid >> 5, lane = tid & 31;
    const int wm = wid >> 2, wn = wid & 3;
    const int g = lane >> 2, t2 = (lane & 3) * 2;
    int mt = blockIdx.x, h = blockIdx.y;
    uint32_t smb = smem_to_u32(sm);
    uint32_t smA = smb;
    uint32_t smB = smb + SC_A_BYTES;

    // ---- load persistent Q tile: 2048 x 16B ----
    {
        const __half* src = g_Q + ((size_t)h * SQ + (size_t)mt * 128) * DK;
#pragma unroll
        for (int j = 0; j < 8; j++) {
            int i = tid + j * 256;
            int row = i >> 4, grp = i & 15;
            int cg = grp >> 2, c4 = grp & 3;
            const void* gp = src + (size_t)row * DK + grp * 8;
            uint32_t sw = (uint32_t)(c4 ^ ((row >> 1) & 3));
            uint32_t s = smA + cg * 8192 + row * ROWB + sw * 16;
            cp16(s, gp);
        }
        CP_COMMIT();
    }

    const __half* B0 = g_K + (size_t)h * LTOT * DK;
    auto load_B = [&](int slot, int it) {
        int t = it >> 2, cc = it & 3;
#pragma unroll
        for (int j = 0; j < 2; j++) {
            int i = tid + j * 256;
            int row = i >> 2, c4 = i & 3;
            const void* gp = B0 + (size_t)(t * 128 + row) * DK + cc * BKT + c4 * 8;
            uint32_t sw = (uint32_t)(c4 ^ ((row >> 1) & 3));
            uint32_t s = smB + slot * SC_BSTAGE + row * ROWB + sw * 16;
            cp16(s, gp);
        }
        CP_COMMIT();
    };

    const uint32_t lrow = (uint32_t)(lane & 15);
    const uint32_t lchunk = (uint32_t)((lane >> 4) & 1);
    const uint32_t arowi = (uint32_t)(wm * 64) + lrow;
    const uint32_t browi = (uint32_t)(wn * 32) + lrow;

    float acc[4][4][4];
#pragma unroll
    for (int mf = 0; mf < 4; mf++)
#pragma unroll
        for (int nf = 0; nf < 4; nf++)
#pragma unroll
            for (int i = 0; i < 4; i++) acc[mf][nf][i] = 0.f;

    load_B(0, 0);
    load_B(1, 1);
    size_t rb = (size_t)h * SQ + (size_t)mt * 128;

#pragma unroll 1
    for (int it = 0; it < 128; it++) {
        CP_WAIT1();
        __syncthreads();
        if (it + 2 < 128) load_B((it + 2) % 3, it + 2);
        else CP_COMMIT();
        {
            uint32_t abase = smA + (uint32_t)(it & 3) * 8192;
            uint32_t bbase = smB + (uint32_t)(it % 3) * SC_BSTAGE;
#pragma unroll
            for (int ks = 0; ks < 2; ks++) {
                uint32_t chunk = (uint32_t)ks * 2 + lchunk;
                uint32_t fa[4][4], fb[2][4];
#pragma unroll
                for (int mf = 0; mf < 4; mf++) {
                    uint32_t row = arowi + mf * 16;
                    uint32_t a = abase + row * ROWB + ((chunk ^ ((row >> 1) & 3)) << 4);
                    ldm_x4(fa[mf], a);
                }
#pragma unroll
                for (int nb = 0; nb < 2; nb++) {
                    uint32_t row = browi + nb * 16;
                    uint32_t b = bbase + row * ROWB + ((chunk ^ ((row >> 1) & 3)) << 4);
                    ldm_x4(fb[nb], b);
                }
#pragma unroll
                for (int mf = 0; mf < 4; mf++)
#pragma unroll
                    for (int nf = 0; nf < 4; nf++) {
                        int nb = nf >> 1, sel = nf & 1;
                        mma16816(acc[mf][nf], fa[mf], fb[nb][sel], fb[nb][2 + sel]);
                    }
            }
        }
        // ---- per-l-tile epilogue (register-only) ----
        if ((it & 3) == 3) {
            int t = it >> 2;
#pragma unroll
            for (int nf = 0; nf < 4; nf++) {
                int col = wn * 32 + nf * 8 + t2;
                float cs0 = 0.f, cs1 = 0.f;
#pragma unroll
                for (int mf = 0; mf < 4; mf++) {
                    int r0 = wm * 64 + mf * 16 + g;
#pragma unroll
                    for (int half = 0; half < 2; half++) {
                        int r = r0 + half * 8;
                        float v0 = __expf(acc[mf][nf][half * 2 + 0] * RSQRT_DK);
                        float v1 = __expf(acc[mf][nf][half * 2 + 1] * RSQRT_DK);
                        __half h0 = __float2half(v0);
                        __half h1 = __float2half(v1);
                        cs0 += __half2float(h0);
                        cs1 += __half2float(h1);
                        size_t o = (rb + r) * LTOT + (size_t)t * 128 + col;
                        *(__half2*)&g_P[o] = __halves2half2(h0, h1);
                        acc[mf][nf][half * 2 + 0] = 0.f;
                        acc[mf][nf][half * 2 + 1] = 0.f;
                    }
                }
#pragma unroll
                for (int off = 4; off < 32; off <<= 1) {
                    cs0 += __shfl_xor_sync(0xffffffffu, cs0, off);
                    cs1 += __shfl_xor_sync(0xffffffffu, cs1, off);
                }
                if (g == 0) {
                    atomicAdd(&g_sum[h * LTOT + t * 128 + col], cs0);
                    atomicAdd(&g_sum[h * LTOT + t * 128 + col + 1], cs1);
                }
            }
        }
    }
}

// ctx: P single x V single -> C single
__global__ void __launch_bounds__(256, 2) k_ctx() {
    extern __shared__ char sm[];
    int mt = blockIdx.x, h = blockIdx.y;
    float acc[4][4][4];
    size_t aoff = ((size_t)h * SQ + (size_t)mt * 128) * LTOT;
    size_t boff = (size_t)h * DK * LTOT;
    gemm_main(g_P + aoff, g_Vt + boff, LTOT, LTOT, LTOT / BKT, sm, acc);
    EPI_COORDS();
#pragma unroll
    for (int mf = 0; mf < 4; mf++)
#pragma unroll
        for (int nf = 0; nf < 4; nf++) {
            int col = wn * 32 + nf * 8 + t2;
            int r0 = wm * 64 + mf * 16 + g;
#pragma unroll
            for (int half = 0; half < 2; half++) {
                int r = r0 + half * 8;
                __half h0 = __float2half(acc[mf][nf][half * 2 + 0]);
                __half h1 = __float2half(acc[mf][nf][half * 2 + 1]);
                size_t o = (size_t)(mt * 128 + r) * DM + (size_t)h * DK + col;
                *(__half2*)&g_C[o] = __halves2half2(h0, h1);
            }
        }
}

// out: C single x Wo single
__global__ void __launch_bounds__(256, 2) k_out(const float* __restrict__ bo,
                                                float* __restrict__ out) {
    extern __shared__ char sm[];
    int nt = blockIdx.x, mt = blockIdx.y;
    float acc[4][4][4];
    gemm_main(g_C + (size_t)mt * 128 * DM, g_Wot + (size_t)nt * 128 * DM,
              DM, DM, DM / BKT, sm, acc);
    EPI_COORDS();
    const float* bop = bo + nt * 128;
#pragma unroll
    for (int mf = 0; mf < 4; mf++)
#pragma unroll
        for (int nf = 0; nf < 4; nf++) {
            int col = wn * 32 + nf * 8 + t2;
            float b0 = bop[col], b1 = bop[col + 1];
            int r0 = wm * 64 + mf * 16 + g;
#pragma unroll
            for (int half = 0; half < 2; half++) {
                int r = r0 + half * 8;
                float2 v;
                v.x = acc[mf][nf][half * 2 + 0] + b0;
                v.y = acc[mf][nf][half * 2 + 1] + b1;
                *(float2*)&out[(size_t)(mt * 128 + r) * DM + (size_t)nt * 128 + col] = v;
            }
        }
}

// ============================ prep kernels ============================
__global__ void prep_init(const float* __restrict__ bk, const float* __restrict__ bv) {
    int i = blockIdx.x * 256 + threadIdx.x;
    if (i < H * DK) { g_kn[i] = bk[i]; g_vn[i] = bv[i]; }
    g_sum[i] = 0.f;
}

__global__ void knv_part(const float* __restrict__ x,
                         const float* __restrict__ Wk, const float* __restrict__ Wv) {
    int h = blockIdx.x, b = blockIdx.y;
    int k = threadIdx.x;
    const float* xl = x + (size_t)(SQ - 1) * DM + b * 512;
    const float* wk = Wk + (size_t)h * DM * DK + (size_t)b * 512 * DK + k;
    const float* wv = Wv + (size_t)h * DM * DK + (size_t)b * 512 * DK + k;
    float aK = 0.f, aV = 0.f;
#pragma unroll 4
    for (int d = 0; d < 512; d++) {
        float xv = xl[d];
        aK += xv * wk[(size_t)d * DK];
        aV += xv * wv[(size_t)d * DK];
    }
    atomicAdd(&g_kn[h * DK + k], aK);
    atomicAdd(&g_vn[h * DK + k], aV);
}

__global__ void conv_x(const float* __restrict__ x) {
    size_t i = (size_t)blockIdx.x * 256 + threadIdx.x;
    g_X[i] = __float2half(x[i]);
}

__global__ void conv_keys(const float* __restrict__ kc, const int* __restrict__ posp) {
    size_t i = (size_t)blockIdx.x * 256 + threadIdx.x;
    int h = (int)(i / ((size_t)LTOT * DK));
    int rem = (int)(i % ((size_t)LTOT * DK));
    int l = rem / DK, dk = rem % DK;
    int pos = posp[0];
    float v = (l == pos) ? g_kn[h * DK + dk] : kc[((size_t)h * MAXSEQ + l) * DK + dk];
    g_K[i] = __float2half(v);
}

__global__ void tconv_wq(const float* __restrict__ W) {
    __shared__ float t[32][33];
    int h = blockIdx.z;
    int c0 = blockIdx.x * 32;
    int r0 = blockIdx.y * 32;
    int tx = threadIdx.x, ty = threadIdx.y;
    const float* in = W + (size_t)h * DM * DK;
#pragma unroll
    for (int i = 0; i < 32; i += 8)
        t[ty + i][tx] = in[(size_t)(r0 + ty + i) * DK + c0 + tx];
    __syncthreads();
    __half* oh = g_Wqt + (size_t)h * DK * DM;
#pragma unroll
    for (int i = 0; i < 32; i += 8) {
        float v = t[tx][ty + i];
        size_t o = (size_t)(c0 + ty + i) * DM + r0 + tx;
        oh[o] = __float2half(v);
    }
}

__global__ void tconv_wo(const float* __restrict__ W) {
    __shared__ float t[32][33];
    int c0 = blockIdx.x * 32;
    int r0 = blockIdx.y * 32;
    int tx = threadIdx.x, ty = threadIdx.y;
#pragma unroll
    for (int i = 0; i < 32; i += 8)
        t[ty + i][tx] = W[(size_t)(r0 + ty + i) * DM + c0 + tx];
    __syncthreads();
#pragma unroll
    for (int i = 0; i < 32; i += 8) {
        float v = t[tx][ty + i];
        size_t o = (size_t)(c0 + ty + i) * DM + r0 + tx;
        g_Wot[o] = __float2half(v);
    }
}

__global__ void tconv_vt(const float* __restrict__ vc, const int* __restrict__ posp) {
    __shared__ float t[32][33];
    int h = blockIdx.z;
    int c0 = blockIdx.x * 32;
    int r0 = blockIdx.y * 32;
    int tx = threadIdx.x, ty = threadIdx.y;
    int pos = posp[0];
#pragma unroll
    for (int i = 0; i < 32; i += 8) {
        int l = r0 + ty + i, dk = c0 + tx;
        float v = (l == pos) ? g_vn[h * DK + dk] : vc[((size_t)h * MAXSEQ + l) * DK + dk];
        t[ty + i][tx] = v * (1.0f / g_sum[h * LTOT + l]);
    }
    __syncthreads();
    __half* oh = g_Vt + (size_t)h * DK * LTOT;
#pragma unroll
    for (int i = 0; i < 32; i += 8) {
        float v = t[tx][ty + i];
        size_t o = (size_t)(c0 + ty + i) * LTOT + r0 + tx;
        oh[o] = __float2half(v);
    }
}

// ============================ launch ============================
extern "C" void kernel_launch(void* const* d_in, const int* in_sizes, int n_in,
                              void* d_out, int out_size) {
    const float* x   = (const float*)d_in[0];
    const float* kc  = (const float*)d_in[1];
    const float* vc  = (const float*)d_in[2];
    const float* Wq  = (const float*)d_in[3];
    const float* bq  = (const float*)d_in[4];
    const float* Wk  = (const float*)d_in[5];
    const float* bk  = (const float*)d_in[6];
    const float* Wv  = (const float*)d_in[7];
    const float* bv  = (const float*)d_in[8];
    const float* Wo  = (const float*)d_in[9];
    const float* bo  = (const float*)d_in[10];
    const int*   pos = (const int*)d_in[11];
    float* out = (float*)d_out;

    const int SM2 = STAGES * 2 * MATB;   // 49152
    cudaFuncSetAttribute(k_qproj,  cudaFuncAttributeMaxDynamicSharedMemorySize, SM2);
    cudaFuncSetAttribute(k_scores, cudaFuncAttributeMaxDynamicSharedMemorySize, SC_SMEM);
    cudaFuncSetAttribute(k_ctx,    cudaFuncAttributeMaxDynamicSharedMemorySize, SM2);
    cudaFuncSetAttribute(k_out,    cudaFuncAttributeMaxDynamicSharedMemorySize, SM2);

    // Fork side stream for memory-bound prep (graph-capturable fork/join).
    // Handles created fresh per call, intentionally not destroyed (see R11 note).
    cudaStream_t s1;
    cudaStreamCreate(&s1);
    cudaEvent_t eFork, eX, eKeys, eWo;
    cudaEventCreateWithFlags(&eFork, cudaEventDisableTiming);
    cudaEventCreateWithFlags(&eX,    cudaEventDisableTiming);
    cudaEventCreateWithFlags(&eKeys, cudaEventDisableTiming);
    cudaEventCreateWithFlags(&eWo,   cudaEventDisableTiming);

    cudaEventRecord(eFork, 0);
    cudaStreamWaitEvent(s1, eFork, 0);

    conv_x<<<(SQ * DM) / 256, 256, 0, s1>>>(x);                           // 1 (s1)
    cudaEventRecord(eX, s1);
    tconv_wq<<<dim3(DK / 32, DM / 32, H), dim3(32, 8)>>>(Wq);             // 2
    prep_init<<<(H * LTOT) / 256, 256, 0, s1>>>(bk, bv);                  // 3 (s1)
    cudaStreamWaitEvent(0, eX, 0);
    k_qproj<<<dim3(H, SQ / 128), 256, SM2>>>(bq);                         // 4 <- profiled
    knv_part<<<dim3(H, 8), DK, 0, s1>>>(x, Wk, Wv);                       // 5 (s1)
    conv_keys<<<(H * LTOT * DK) / 256, 256, 0, s1>>>(kc, pos);            // 6 (s1)
    cudaEventRecord(eKeys, s1);
    tconv_wo<<<dim3(DM / 32, DM / 32), dim3(32, 8), 0, s1>>>(Wo);         // 7 (s1)
    cudaEventRecord(eWo, s1);

    cudaStreamWaitEvent(0, eKeys, 0);
    k_scores<<<dim3(SQ / 128, H), 256, SC_SMEM>>>();                      // 8
    tconv_vt<<<dim3(DK / 32, LTOT / 32, H), dim3(32, 8)>>>(vc, pos);      // 9
    k_ctx<<<dim3(SQ / 128, H), 256, SM2>>>();                             // 10
    cudaStreamWaitEvent(0, eWo, 0);
    k_out<<<dim3(DM / 128, SQ / 128), 256, SM2>>>(bo, out);               // 11
}

// round 14
// speedup vs baseline: 1.0946x; 1.0946x over previous
#include <cuda_runtime.h>
#include <cuda_fp16.h>
#include <math.h>
#include <cstdint>

#define H 32
#define DM 4096
#define DK 128
#define SQ 1024
#define LTOT 4096
#define MAXSEQ 8192
#define RSQRT_DK 0.08838834764831845f
// RSQRT_DK * log2(e): scores epilogue uses exp2f(x * SC_LOG2E) == exp(x * RSQRT_DK)
#define SC_LOG2E 0.1275260257039059f

// GEMM tiling: CTA 128x128, warp tile 64x32 (2x4 warps), BK=32, 3 stages, 2 CTAs/SM
// smem rows: 64B (32 fp16) with XOR swizzle (group ^= (row>>1)&3)
#define STAGES 3
#define BKT 32
#define ROWB 64
#define MATB (128 * ROWB)            // 8192 B per matrix tile (128 rows x 32 k)

// ============================ scratch (device globals) ============================
__device__ __align__(16) __half g_X[(size_t)SQ * DM];
__device__ __align__(16) __half g_Wqt[(size_t)H * DK * DM];
__device__ __align__(16) __half g_K[(size_t)H * LTOT * DK];
__device__ __align__(16) __half g_Q[(size_t)H * SQ * DK];
__device__ __align__(16) __half g_P[(size_t)H * SQ * LTOT];
__device__ __align__(16) __half g_Vt[(size_t)H * DK * LTOT];
__device__ __align__(16) __half g_C[(size_t)SQ * DM];
__device__ __align__(16) __half g_Wot[(size_t)DM * DM];
__device__ float g_sum[H * LTOT];
__device__ float g_kn[H * DK], g_vn[H * DK];

// ============================ helpers ============================
__device__ __forceinline__ uint32_t smem_to_u32(const void* p) {
    uint32_t a;
    asm("{ .reg .u64 t; cvta.to.shared.u64 t, %1; cvt.u32.u64 %0, t; }" : "=r"(a) : "l"(p));
    return a;
}

__device__ __forceinline__ void ldm_x4(uint32_t (&r)[4], uint32_t addr) {
    asm volatile("ldmatrix.sync.aligned.m8n8.x4.shared.b16 {%0,%1,%2,%3}, [%4];"
                 : "=r"(r[0]), "=r"(r[1]), "=r"(r[2]), "=r"(r[3]) : "r"(addr));
}

__device__ __forceinline__ void mma16816(float (&d)[4], const uint32_t (&a)[4],
                                         uint32_t b0, uint32_t b1) {
    asm volatile(
        "mma.sync.aligned.m16n8k16.row.col.f32.f16.f16.f32 "
        "{%0,%1,%2,%3}, {%4,%5,%6,%7}, {%8,%9}, {%0,%1,%2,%3};"
        : "+f"(d[0]), "+f"(d[1]), "+f"(d[2]), "+f"(d[3])
        : "r"(a[0]), "r"(a[1]), "r"(a[2]), "r"(a[3]), "r"(b0), "r"(b1));
}

__device__ __forceinline__ void cp16(uint32_t s, const void* g) {
    asm volatile("cp.async.ca.shared.global [%0], [%1], 16;" :: "r"(s), "l"(g));
}
#define CP_COMMIT() asm volatile("cp.async.commit_group;" ::: "memory")
#define CP_WAIT1()  asm volatile("cp.async.wait_group 1;" ::: "memory")

// ============================ GEMM mainloop (1-term fp16) ============================
// acc[4][4][4] += sum over K of A[m][k] * B[n][k]. CTA 128x128, warp tile 64x32.
__device__ __forceinline__ void gemm_main(
    const __half* __restrict__ A0, const __half* __restrict__ B0,
    int lda, int ldb, int ktiles, char* sm, float (&acc)[4][4][4])
{
    constexpr int STAGEB = 2 * MATB;
    const int tid = threadIdx.x;
    const int wid = tid >> 5, lane = tid & 31;
    const int wm = wid >> 2, wn = wid & 3;
    uint32_t smb = smem_to_u32(sm);

#pragma unroll
    for (int mf = 0; mf < 4; mf++)
#pragma unroll
        for (int nf = 0; nf < 4; nf++)
#pragma unroll
            for (int i = 0; i < 4; i++) acc[mf][nf][i] = 0.f;

    auto load_stage = [&](int slot, int c) {
#pragma unroll
        for (int j = 0; j < 4; j++) {
            int i = tid + j * 256;
            int mat = i >> 9;
            int rem = i & 511;
            int row = rem >> 2, c4 = rem & 3;
            const __half* src = mat ? B0 : A0;
            int ld = mat ? ldb : lda;
            const void* g = src + (size_t)row * ld + (size_t)c * BKT + c4 * 8;
            uint32_t sw = (uint32_t)(c4 ^ ((row >> 1) & 3));
            uint32_t s = smb + slot * STAGEB + mat * MATB + row * ROWB + sw * 16;
            cp16(s, g);
        }
        CP_COMMIT();
    };

    const uint32_t lrow = (uint32_t)(lane & 15);
    const uint32_t lchunk = (uint32_t)((lane >> 4) & 1);
    const uint32_t arowi = (uint32_t)(wm * 64) + lrow;
    const uint32_t browi = (uint32_t)(wn * 32) + lrow;

    auto compute = [&](int slot) {
        uint32_t base = smb + slot * STAGEB;
#pragma unroll
        for (int ks = 0; ks < 2; ks++) {
            uint32_t chunk = (uint32_t)ks * 2 + lchunk;
            uint32_t fa[4][4], fb[2][4];
#pragma unroll
            for (int mf = 0; mf < 4; mf++) {
                uint32_t row = arowi + mf * 16;
                uint32_t a = base + row * ROWB + ((chunk ^ ((row >> 1) & 3)) << 4);
                ldm_x4(fa[mf], a);
            }
#pragma unroll
            for (int nb = 0; nb < 2; nb++) {
                uint32_t row = browi + nb * 16;
                uint32_t b = base + MATB + row * ROWB + ((chunk ^ ((row >> 1) & 3)) << 4);
                ldm_x4(fb[nb], b);
            }
#pragma unroll
            for (int mf = 0; mf < 4; mf++)
#pragma unroll
                for (int nf = 0; nf < 4; nf++) {
                    int nb = nf >> 1, sel = nf & 1;
                    mma16816(acc[mf][nf], fa[mf], fb[nb][sel], fb[nb][2 + sel]);
                }
        }
    };

    load_stage(0, 0);
    if (ktiles > 1) load_stage(1, 1);
    else CP_COMMIT();
#pragma unroll 1
    for (int c = 0; c < ktiles; c++) {
        CP_WAIT1();
        __syncthreads();
        if (c + 2 < ktiles) load_stage((c + 2) % 3, c + 2);
        else CP_COMMIT();
        compute(c % 3);
    }
}

#define EPI_COORDS() \
    const int tid = threadIdx.x; \
    const int wid = tid >> 5, lane = tid & 31; \
    const int wm = wid >> 2, wn = wid & 3; \
    const int g = lane >> 2, t2 = (lane & 3) * 2;

// ============================ GEMM kernels ============================
// qproj: X single x Wq single -> Q single
__global__ void __launch_bounds__(256, 2) k_qproj(const float* __restrict__ bq) {
    extern __shared__ char sm[];
    int h = blockIdx.x, mt = blockIdx.y;
    float acc[4][4][4];
    gemm_main(g_X + (size_t)mt * 128 * DM, g_Wqt + (size_t)h * DK * DM,
              DM, DM, DM / BKT, sm, acc);
    EPI_COORDS();
    const float* bqp = bq + h * DK;
    size_t rb = (size_t)h * SQ + (size_t)mt * 128;
#pragma unroll
    for (int mf = 0; mf < 4; mf++)
#pragma unroll
        for (int nf = 0; nf < 4; nf++) {
            int col = wn * 32 + nf * 8 + t2;
            float b0 = bqp[col], b1 = bqp[col + 1];
            int r0 = wm * 64 + mf * 16 + g;
#pragma unroll
            for (int half = 0; half < 2; half++) {
                int r = r0 + half * 8;
                __half h0 = __float2half(acc[mf][nf][half * 2 + 0] + b0);
                __half h1 = __float2half(acc[mf][nf][half * 2 + 1] + b1);
                size_t o = (rb + r) * DK + col;
                *(__half2*)&g_Q[o] = __halves2half2(h0, h1);
            }
        }
}

// ======================= scores: persistent-Q streaming kernel =======================
#define SC_A_BYTES 32768                      // Q single: 4 chunk-blocks x MATB
#define SC_BSTAGE  8192                       // K single: 1 mat x MATB
#define SC_SMEM (SC_A_BYTES + 3 * SC_BSTAGE)  // 57344

__global__ void __launch_bounds__(256, 2) k_scores() {
    extern __shared__ char sm[];
    const int tid = threadIdx.x;
    const int wid = tid >> 5, lane = tid & 31;
    const int wm = wid >> 2, wn = wid & 3;
    const int g = lane >> 2, t2 = (lane & 3) * 2;
    int mt = blockIdx.x, h = blockIdx.y;
    uint32_t smb = smem_to_u32(sm);
    uint32_t smA = smb;
    uint32_t smB = smb + SC_A_BYTES;

    // ---- load persistent Q tile: 2048 x 16B ----
    {
        const __half* src = g_Q + ((size_t)h * SQ + (size_t)mt * 128) * DK;
#pragma unroll
        for (int j = 0; j < 8; j++) {
            int i = tid + j * 256;
            int row = i >> 4, grp = i & 15;
            int cg = grp >> 2, c4 = grp & 3;
            const void* gp = src + (size_t)row * DK + grp * 8;
            uint32_t sw = (uint32_t)(c4 ^ ((row >> 1) & 3));
            uint32_t s = smA + cg * 8192 + row * ROWB + sw * 16;
            cp16(s, gp);
        }
        CP_COMMIT();
    }

    const __half* B0 = g_K + (size_t)h * LTOT * DK;
    auto load_B = [&](int slot, int it) {
        int t = it >> 2, cc = it & 3;
#pragma unroll
        for (int j = 0; j < 2; j++) {
            int i = tid + j * 256;
            int row = i >> 2, c4 = i & 3;
            const void* gp = B0 + (size_t)(t * 128 + row) * DK + cc * BKT + c4 * 8;
            uint32_t sw = (uint32_t)(c4 ^ ((row >> 1) & 3));
            uint32_t s = smB + slot * SC_BSTAGE + row * ROWB + sw * 16;
            cp16(s, gp);
        }
        CP_COMMIT();
    };

    const uint32_t lrow = (uint32_t)(lane & 15);
    const uint32_t lchunk = (uint32_t)((lane >> 4) & 1);
    const uint32_t arowi = (uint32_t)(wm * 64) + lrow;
    const uint32_t browi = (uint32_t)(wn * 32) + lrow;

    float acc[4][4][4];
#pragma unroll
    for (int mf = 0; mf < 4; mf++)
#pragma unroll
        for (int nf = 0; nf < 4; nf++)
#pragma unroll
            for (int i = 0; i < 4; i++) acc[mf][nf][i] = 0.f;

    load_B(0, 0);
    load_B(1, 1);
    size_t rb = (size_t)h * SQ + (size_t)mt * 128;

#pragma unroll 1
    for (int it = 0; it < 128; it++) {
        CP_WAIT1();
        __syncthreads();
        if (it + 2 < 128) load_B((it + 2) % 3, it + 2);
        else CP_COMMIT();
        {
            uint32_t abase = smA + (uint32_t)(it & 3) * 8192;
            uint32_t bbase = smB + (uint32_t)(it % 3) * SC_BSTAGE;
#pragma unroll
            for (int ks = 0; ks < 2; ks++) {
                uint32_t chunk = (uint32_t)ks * 2 + lchunk;
                uint32_t fa[4][4], fb[2][4];
#pragma unroll
                for (int mf = 0; mf < 4; mf++) {
                    uint32_t row = arowi + mf * 16;
                    uint32_t a = abase + row * ROWB + ((chunk ^ ((row >> 1) & 3)) << 4);
                    ldm_x4(fa[mf], a);
                }
#pragma unroll
                for (int nb = 0; nb < 2; nb++) {
                    uint32_t row = browi + nb * 16;
                    uint32_t b = bbase + row * ROWB + ((chunk ^ ((row >> 1) & 3)) << 4);
                    ldm_x4(fb[nb], b);
                }
#pragma unroll
                for (int mf = 0; mf < 4; mf++)
#pragma unroll
                    for (int nf = 0; nf < 4; nf++) {
                        int nb = nf >> 1, sel = nf & 1;
                        mma16816(acc[mf][nf], fa[mf], fb[nb][sel], fb[nb][2 + sel]);
                    }
            }
        }
        // ---- per-l-tile epilogue (register-only) ----
        if ((it & 3) == 3) {
            int t = it >> 2;
#pragma unroll
            for (int nf = 0; nf < 4; nf++) {
                int col = wn * 32 + nf * 8 + t2;
                float cs0 = 0.f, cs1 = 0.f;
#pragma unroll
                for (int mf = 0; mf < 4; mf++) {
                    int r0 = wm * 64 + mf * 16 + g;
#pragma unroll
                    for (int half = 0; half < 2; half++) {
                        int r = r0 + half * 8;
                        float v0 = exp2f(acc[mf][nf][half * 2 + 0] * SC_LOG2E);
                        float v1 = exp2f(acc[mf][nf][half * 2 + 1] * SC_LOG2E);
                        __half h0 = __float2half(v0);
                        __half h1 = __float2half(v1);
                        cs0 += __half2float(h0);
                        cs1 += __half2float(h1);
                        size_t o = (rb + r) * LTOT + (size_t)t * 128 + col;
                        *(__half2*)&g_P[o] = __halves2half2(h0, h1);
                        acc[mf][nf][half * 2 + 0] = 0.f;
                        acc[mf][nf][half * 2 + 1] = 0.f;
                    }
                }
#pragma unroll
                for (int off = 4; off < 32; off <<= 1) {
                    cs0 += __shfl_xor_sync(0xffffffffu, cs0, off);
                    cs1 += __shfl_xor_sync(0xffffffffu, cs1, off);
                }
                if (g == 0) {
                    atomicAdd(&g_sum[h * LTOT + t * 128 + col], cs0);
                    atomicAdd(&g_sum[h * LTOT + t * 128 + col + 1], cs1);
                }
            }
        }
    }
}

// ctx: P single x V single -> C single
__global__ void __launch_bounds__(256, 2) k_ctx() {
    extern __shared__ char sm[];
    int mt = blockIdx.x, h = blockIdx.y;
    float acc[4][4][4];
    size_t aoff = ((size_t)h * SQ + (size_t)mt * 128) * LTOT;
    size_t boff = (size_t)h * DK * LTOT;
    gemm_main(g_P + aoff, g_Vt + boff, LTOT, LTOT, LTOT / BKT, sm, acc);
    EPI_COORDS();
#pragma unroll
    for (int mf = 0; mf < 4; mf++)
#pragma unroll
        for (int nf = 0; nf < 4; nf++) {
            int col = wn * 32 + nf * 8 + t2;
            int r0 = wm * 64 + mf * 16 + g;
#pragma unroll
            for (int half = 0; half < 2; half++) {
                int r = r0 + half * 8;
                __half h0 = __float2half(acc[mf][nf][half * 2 + 0]);
                __half h1 = __float2half(acc[mf][nf][half * 2 + 1]);
                size_t o = (size_t)(mt * 128 + r) * DM + (size_t)h * DK + col;
                *(__half2*)&g_C[o] = __halves2half2(h0, h1);
            }
        }
}

// out: C single x Wo single
__global__ void __launch_bounds__(256, 2) k_out(const float* __restrict__ bo,
                                                float* __restrict__ out) {
    extern __shared__ char sm[];
    int nt = blockIdx.x, mt = blockIdx.y;
    float acc[4][4][4];
    gemm_main(g_C + (size_t)mt * 128 * DM, g_Wot + (size_t)nt * 128 * DM,
              DM, DM, DM / BKT, sm, acc);
    EPI_COORDS();
    const float* bop = bo + nt * 128;
#pragma unroll
    for (int mf = 0; mf < 4; mf++)
#pragma unroll
        for (int nf = 0; nf < 4; nf++) {
            int col = wn * 32 + nf * 8 + t2;
            float b0 = bop[col], b1 = bop[col + 1];
            int r0 = wm * 64 + mf * 16 + g;
#pragma unroll
            for (int half = 0; half < 2; half++) {
                int r = r0 + half * 8;
                float2 v;
                v.x = acc[mf][nf][half * 2 + 0] + b0;
                v.y = acc[mf][nf][half * 2 + 1] + b1;
                *(float2*)&out[(size_t)(mt * 128 + r) * DM + (size_t)nt * 128 + col] = v;
            }
        }
}

// ============================ prep kernels ============================
__global__ void prep_init(const float* __restrict__ bk, const float* __restrict__ bv) {
    int i = blockIdx.x * 256 + threadIdx.x;
    if (i < H * DK) { g_kn[i] = bk[i]; g_vn[i] = bv[i]; }
    g_sum[i] = 0.f;
}

__global__ void knv_part(const float* __restrict__ x,
                         const float* __restrict__ Wk, const float* __restrict__ Wv) {
    int h = blockIdx.x, b = blockIdx.y;
    int k = threadIdx.x;
    const float* xl = x + (size_t)(SQ - 1) * DM + b * 512;
    const float* wk = Wk + (size_t)h * DM * DK + (size_t)b * 512 * DK + k;
    const float* wv = Wv + (size_t)h * DM * DK + (size_t)b * 512 * DK + k;
    float aK = 0.f, aV = 0.f;
#pragma unroll 4
    for (int d = 0; d < 512; d++) {
        float xv = xl[d];
        aK += xv * wk[(size_t)d * DK];
        aV += xv * wv[(size_t)d * DK];
    }
    atomicAdd(&g_kn[h * DK + k], aK);
    atomicAdd(&g_vn[h * DK + k], aV);
}

__global__ void conv_x(const float* __restrict__ x) {
    size_t i = (size_t)blockIdx.x * 256 + threadIdx.x;
    g_X[i] = __float2half(x[i]);
}

__global__ void conv_keys(const float* __restrict__ kc, const int* __restrict__ posp) {
    size_t i = (size_t)blockIdx.x * 256 + threadIdx.x;
    int h = (int)(i / ((size_t)LTOT * DK));
    int rem = (int)(i % ((size_t)LTOT * DK));
    int l = rem / DK, dk = rem % DK;
    int pos = posp[0];
    float v = (l == pos) ? g_kn[h * DK + dk] : kc[((size_t)h * MAXSEQ + l) * DK + dk];
    g_K[i] = __float2half(v);
}

__global__ void tconv_wq(const float* __restrict__ W) {
    __shared__ float t[32][33];
    int h = blockIdx.z;
    int c0 = blockIdx.x * 32;
    int r0 = blockIdx.y * 32;
    int tx = threadIdx.x, ty = threadIdx.y;
    const float* in = W + (size_t)h * DM * DK;
#pragma unroll
    for (int i = 0; i < 32; i += 8)
        t[ty + i][tx] = in[(size_t)(r0 + ty + i) * DK + c0 + tx];
    __syncthreads();
    __half* oh = g_Wqt + (size_t)h * DK * DM;
#pragma unroll
    for (int i = 0; i < 32; i += 8) {
        float v = t[tx][ty + i];
        size_t o = (size_t)(c0 + ty + i) * DM + r0 + tx;
        oh[o] = __float2half(v);
    }
}

__global__ void tconv_wo(const float* __restrict__ W) {
    __shared__ float t[32][33];
    int c0 = blockIdx.x * 32;
    int r0 = blockIdx.y * 32;
    int tx = threadIdx.x, ty = threadIdx.y;
#pragma unroll
    for (int i = 0; i < 32; i += 8)
        t[ty + i][tx] = W[(size_t)(r0 + ty + i) * DM + c0 + tx];
    __syncthreads();
#pragma unroll
    for (int i = 0; i < 32; i += 8) {
        float v = t[tx][ty + i];
        size_t o = (size_t)(c0 + ty + i) * DM + r0 + tx;
        g_Wot[o] = __float2half(v);
    }
}

__global__ void tconv_vt(const float* __restrict__ vc, const int* __restrict__ posp) {
    __shared__ float t[32][33];
    int h = blockIdx.z;
    int c0 = blockIdx.x * 32;
    int r0 = blockIdx.y * 32;
    int tx = threadIdx.x, ty = threadIdx.y;
    int pos = posp[0];
#pragma unroll
    for (int i = 0; i < 32; i += 8) {
        int l = r0 + ty + i, dk = c0 + tx;
        float v = (l == pos) ? g_vn[h * DK + dk] : vc[((size_t)h * MAXSEQ + l) * DK + dk];
        t[ty + i][tx] = v * (1.0f / g_sum[h * LTOT + l]);
    }
    __syncthreads();
    __half* oh = g_Vt + (size_t)h * DK * LTOT;
#pragma unroll
    for (int i = 0; i < 32; i += 8) {
        float v = t[tx][ty + i];
        size_t o = (size_t)(c0 + ty + i) * LTOT + r0 + tx;
        oh[o] = __float2half(v);
    }
}

// ============================ launch ============================
extern "C" void kernel_launch(void* const* d_in, const int* in_sizes, int n_in,
                              void* d_out, int out_size) {
    const float* x   = (const float*)d_in[0];
    const float* kc  = (const float*)d_in[1];
    const float* vc  = (const float*)d_in[2];
    const float* Wq  = (const float*)d_in[3];
    const float* bq  = (const float*)d_in[4];
    const float* Wk  = (const float*)d_in[5];
    const float* bk  = (const float*)d_in[6];
    const float* Wv  = (const float*)d_in[7];
    const float* bv  = (const float*)d_in[8];
    const float* Wo  = (const float*)d_in[9];
    const float* bo  = (const float*)d_in[10];
    const int*   pos = (const int*)d_in[11];
    float* out = (float*)d_out;

    const int SM2 = STAGES * 2 * MATB;   // 49152
    cudaFuncSetAttribute(k_qproj,  cudaFuncAttributeMaxDynamicSharedMemorySize, SM2);
    cudaFuncSetAttribute(k_scores, cudaFuncAttributeMaxDynamicSharedMemorySize, SC_SMEM);
    cudaFuncSetAttribute(k_ctx,    cudaFuncAttributeMaxDynamicSharedMemorySize, SM2);
    cudaFuncSetAttribute(k_out,    cudaFuncAttributeMaxDynamicSharedMemorySize, SM2);

    // R11 launch topology exactly (best measured: 696.4 us).
    // Handles created fresh per call, intentionally not destroyed (see R11 note).
    cudaStream_t s1;
    cudaStreamCreate(&s1);
    cudaEvent_t eFork, eKeys, eWo;
    cudaEventCreateWithFlags(&eFork, cudaEventDisableTiming);
    cudaEventCreateWithFlags(&eKeys, cudaEventDisableTiming);
    cudaEventCreateWithFlags(&eWo,   cudaEventDisableTiming);

    cudaEventRecord(eFork, 0);
    cudaStreamWaitEvent(s1, eFork, 0);

    // main stream: conv_x -> tconv_wq -> k_qproj (k_qproj is 4th launch = ncu slot)
    conv_x<<<(SQ * DM) / 256, 256>>>(x);                                  // 1
    tconv_wq<<<dim3(DK / 32, DM / 32, H), dim3(32, 8)>>>(Wq);             // 2
    prep_init<<<(H * LTOT) / 256, 256, 0, s1>>>(bk, bv);                  // 3 (s1)
    k_qproj<<<dim3(H, SQ / 128), 256, SM2>>>(bq);                         // 4 <- profiled
    knv_part<<<dim3(H, 8), DK, 0, s1>>>(x, Wk, Wv);                       // 5 (s1)
    conv_keys<<<(H * LTOT * DK) / 256, 256, 0, s1>>>(kc, pos);            // 6 (s1)
    cudaEventRecord(eKeys, s1);
    tconv_wo<<<dim3(DM / 32, DM / 32), dim3(32, 8), 0, s1>>>(Wo);         // 7 (s1)
    cudaEventRecord(eWo, s1);

    cudaStreamWaitEvent(0, eKeys, 0);
    k_scores<<<dim3(SQ / 128, H), 256, SC_SMEM>>>();                      // 8
    tconv_vt<<<dim3(DK / 32, LTOT / 32, H), dim3(32, 8)>>>(vc, pos);      // 9
    k_ctx<<<dim3(SQ / 128, H), 256, SM2>>>();                             // 10
    cudaStreamWaitEvent(0, eWo, 0);
    k_out<<<dim3(DM / 128, SQ / 128), 256, SM2>>>(bo, out);               // 11
}

// round 15
// speedup vs baseline: 1.1111x; 1.0151x over previous
#include <cuda_runtime.h>
#include <cuda_fp16.h>
#include <math.h>
#include <cstdint>

#define H 32
#define DM 4096
#define DK 128
#define SQ 1024
#define LTOT 4096
#define MAXSEQ 8192
#define RSQRT_DK 0.08838834764831845f
// RSQRT_DK * log2(e): scores epilogue uses exp2f(x * SC_LOG2E) == exp(x * RSQRT_DK)
#define SC_LOG2E 0.1275260257039059f

// GEMM tiling: CTA 128x128, warp tile 64x32 (2x4 warps), BK=32, 3 stages, 2 CTAs/SM
// smem rows: 64B (32 fp16) with XOR swizzle (group ^= (row>>1)&3)
#define STAGES 3
#define BKT 32
#define ROWB 64
#define MATB (128 * ROWB)            // 8192 B per matrix tile (128 rows x 32 k)

// ============================ scratch (device globals) ============================
__device__ __align__(16) __half g_X[(size_t)SQ * DM];
__device__ __align__(16) __half g_Wqt[(size_t)H * DK * DM];
__device__ __align__(16) __half g_K[(size_t)H * LTOT * DK];
__device__ __align__(16) __half g_Q[(size_t)H * SQ * DK];
__device__ __align__(16) __half g_P[(size_t)H * SQ * LTOT];
__device__ __align__(16) float  g_VtF[(size_t)H * DK * LTOT];   // unscaled V^T (fp32)
__device__ __align__(16) __half g_Vt[(size_t)H * DK * LTOT];
__device__ __align__(16) __half g_C[(size_t)SQ * DM];
__device__ __align__(16) __half g_Wot[(size_t)DM * DM];
__device__ float g_sum[H * LTOT];
__device__ float g_kn[H * DK], g_vn[H * DK];

// ============================ helpers ============================
__device__ __forceinline__ uint32_t smem_to_u32(const void* p) {
    uint32_t a;
    asm("{ .reg .u64 t; cvta.to.shared.u64 t, %1; cvt.u32.u64 %0, t; }" : "=r"(a) : "l"(p));
    return a;
}

__device__ __forceinline__ void ldm_x4(uint32_t (&r)[4], uint32_t addr) {
    asm volatile("ldmatrix.sync.aligned.m8n8.x4.shared.b16 {%0,%1,%2,%3}, [%4];"
                 : "=r"(r[0]), "=r"(r[1]), "=r"(r[2]), "=r"(r[3]) : "r"(addr));
}

__device__ __forceinline__ void mma16816(float (&d)[4], const uint32_t (&a)[4],
                                         uint32_t b0, uint32_t b1) {
    asm volatile(
        "mma.sync.aligned.m16n8k16.row.col.f32.f16.f16.f32 "
        "{%0,%1,%2,%3}, {%4,%5,%6,%7}, {%8,%9}, {%0,%1,%2,%3};"
        : "+f"(d[0]), "+f"(d[1]), "+f"(d[2]), "+f"(d[3])
        : "r"(a[0]), "r"(a[1]), "r"(a[2]), "r"(a[3]), "r"(b0), "r"(b1));
}

__device__ __forceinline__ void cp16(uint32_t s, const void* g) {
    asm volatile("cp.async.ca.shared.global [%0], [%1], 16;" :: "r"(s), "l"(g));
}
#define CP_COMMIT() asm volatile("cp.async.commit_group;" ::: "memory")
#define CP_WAIT1()  asm volatile("cp.async.wait_group 1;" ::: "memory")

// ============================ GEMM mainloop (1-term fp16) ============================
// acc[4][4][4] += sum over K of A[m][k] * B[n][k]. CTA 128x128, warp tile 64x32.
__device__ __forceinline__ void gemm_main(
    const __half* __restrict__ A0, const __half* __restrict__ B0,
    int lda, int ldb, int ktiles, char* sm, float (&acc)[4][4][4])
{
    constexpr int STAGEB = 2 * MATB;
    const int tid = threadIdx.x;
    const int wid = tid >> 5, lane = tid & 31;
    const int wm = wid >> 2, wn = wid & 3;
    uint32_t smb = smem_to_u32(sm);

#pragma unroll
    for (int mf = 0; mf < 4; mf++)
#pragma unroll
        for (int nf = 0; nf < 4; nf++)
#pragma unroll
            for (int i = 0; i < 4; i++) acc[mf][nf][i] = 0.f;

    auto load_stage = [&](int slot, int c) {
#pragma unroll
        for (int j = 0; j < 4; j++) {
            int i = tid + j * 256;
            int mat = i >> 9;
            int rem = i & 511;
            int row = rem >> 2, c4 = rem & 3;
            const __half* src = mat ? B0 : A0;
            int ld = mat ? ldb : lda;
            const void* g = src + (size_t)row * ld + (size_t)c * BKT + c4 * 8;
            uint32_t sw = (uint32_t)(c4 ^ ((row >> 1) & 3));
            uint32_t s = smb + slot * STAGEB + mat * MATB + row * ROWB + sw * 16;
            cp16(s, g);
        }
        CP_COMMIT();
    };

    const uint32_t lrow = (uint32_t)(lane & 15);
    const uint32_t lchunk = (uint32_t)((lane >> 4) & 1);
    const uint32_t arowi = (uint32_t)(wm * 64) + lrow;
    const uint32_t browi = (uint32_t)(wn * 32) + lrow;

    auto compute = [&](int slot) {
        uint32_t base = smb + slot * STAGEB;
#pragma unroll
        for (int ks = 0; ks < 2; ks++) {
            uint32_t chunk = (uint32_t)ks * 2 + lchunk;
            uint32_t fa[4][4], fb[2][4];
#pragma unroll
            for (int mf = 0; mf < 4; mf++) {
                uint32_t row = arowi + mf * 16;
                uint32_t a = base + row * ROWB + ((chunk ^ ((row >> 1) & 3)) << 4);
                ldm_x4(fa[mf], a);
            }
#pragma unroll
            for (int nb = 0; nb < 2; nb++) {
                uint32_t row = browi + nb * 16;
                uint32_t b = base + MATB + row * ROWB + ((chunk ^ ((row >> 1) & 3)) << 4);
                ldm_x4(fb[nb], b);
            }
#pragma unroll
            for (int mf = 0; mf < 4; mf++)
#pragma unroll
                for (int nf = 0; nf < 4; nf++) {
                    int nb = nf >> 1, sel = nf & 1;
                    mma16816(acc[mf][nf], fa[mf], fb[nb][sel], fb[nb][2 + sel]);
                }
        }
    };

    load_stage(0, 0);
    if (ktiles > 1) load_stage(1, 1);
    else CP_COMMIT();
#pragma unroll 1
    for (int c = 0; c < ktiles; c++) {
        CP_WAIT1();
        __syncthreads();
        if (c + 2 < ktiles) load_stage((c + 2) % 3, c + 2);
        else CP_COMMIT();
        compute(c % 3);
    }
}

#define EPI_COORDS() \
    const int tid = threadIdx.x; \
    const int wid = tid >> 5, lane = tid & 31; \
    const int wm = wid >> 2, wn = wid & 3; \
    const int g = lane >> 2, t2 = (lane & 3) * 2;

// ============================ GEMM kernels ============================
// qproj: X single x Wq single -> Q single
__global__ void __launch_bounds__(256, 2) k_qproj(const float* __restrict__ bq) {
    extern __shared__ char sm[];
    int h = blockIdx.x, mt = blockIdx.y;
    float acc[4][4][4];
    gemm_main(g_X + (size_t)mt * 128 * DM, g_Wqt + (size_t)h * DK * DM,
              DM, DM, DM / BKT, sm, acc);
    EPI_COORDS();
    const float* bqp = bq + h * DK;
    size_t rb = (size_t)h * SQ + (size_t)mt * 128;
#pragma unroll
    for (int mf = 0; mf < 4; mf++)
#pragma unroll
        for (int nf = 0; nf < 4; nf++) {
            int col = wn * 32 + nf * 8 + t2;
            float b0 = bqp[col], b1 = bqp[col + 1];
            int r0 = wm * 64 + mf * 16 + g;
#pragma unroll
            for (int half = 0; half < 2; half++) {
                int r = r0 + half * 8;
                __half h0 = __float2half(acc[mf][nf][half * 2 + 0] + b0);
                __half h1 = __float2half(acc[mf][nf][half * 2 + 1] + b1);
                size_t o = (rb + r) * DK + col;
                *(__half2*)&g_Q[o] = __halves2half2(h0, h1);
            }
        }
}

// ======================= scores: persistent-Q streaming kernel =======================
#define SC_A_BYTES 32768                      // Q single: 4 chunk-blocks x MATB
#define SC_BSTAGE  8192                       // K single: 1 mat x MATB
#define SC_SMEM (SC_A_BYTES + 3 * SC_BSTAGE)  // 57344

__global__ void __launch_bounds__(256, 2) k_scores() {
    extern __shared__ char sm[];
    const int tid = threadIdx.x;
    const int wid = tid >> 5, lane = tid & 31;
    const int wm = wid >> 2, wn = wid & 3;
    const int g = lane >> 2, t2 = (lane & 3) * 2;
    int mt = blockIdx.x, h = blockIdx.y;
    uint32_t smb = smem_to_u32(sm);
    uint32_t smA = smb;
    uint32_t smB = smb + SC_A_BYTES;

    // ---- load persistent Q tile: 2048 x 16B ----
    {
        const __half* src = g_Q + ((size_t)h * SQ + (size_t)mt * 128) * DK;
#pragma unroll
        for (int j = 0; j < 8; j++) {
            int i = tid + j * 256;
            int row = i >> 4, grp = i & 15;
            int cg = grp >> 2, c4 = grp & 3;
            const void* gp = src + (size_t)row * DK + grp * 8;
            uint32_t sw = (uint32_t)(c4 ^ ((row >> 1) & 3));
            uint32_t s = smA + cg * 8192 + row * ROWB + sw * 16;
            cp16(s, gp);
        }
        CP_COMMIT();
    }

    const __half* B0 = g_K + (size_t)h * LTOT * DK;
    auto load_B = [&](int slot, int it) {
        int t = it >> 2, cc = it & 3;
#pragma unroll
        for (int j = 0; j < 2; j++) {
            int i = tid + j * 256;
            int row = i >> 2, c4 = i & 3;
            const void* gp = B0 + (size_t)(t * 128 + row) * DK + cc * BKT + c4 * 8;
            uint32_t sw = (uint32_t)(c4 ^ ((row >> 1) & 3));
            uint32_t s = smB + slot * SC_BSTAGE + row * ROWB + sw * 16;
            cp16(s, gp);
        }
        CP_COMMIT();
    };

    const uint32_t lrow = (uint32_t)(lane & 15);
    const uint32_t lchunk = (uint32_t)((lane >> 4) & 1);
    const uint32_t arowi = (uint32_t)(wm * 64) + lrow;
    const uint32_t browi = (uint32_t)(wn * 32) + lrow;

    float acc[4][4][4];
#pragma unroll
    for (int mf = 0; mf < 4; mf++)
#pragma unroll
        for (int nf = 0; nf < 4; nf++)
#pragma unroll
            for (int i = 0; i < 4; i++) acc[mf][nf][i] = 0.f;

    load_B(0, 0);
    load_B(1, 1);
    size_t rb = (size_t)h * SQ + (size_t)mt * 128;

#pragma unroll 1
    for (int it = 0; it < 128; it++) {
        CP_WAIT1();
        __syncthreads();
        if (it + 2 < 128) load_B((it + 2) % 3, it + 2);
        else CP_COMMIT();
        {
            uint32_t abase = smA + (uint32_t)(it & 3) * 8192;
            uint32_t bbase = smB + (uint32_t)(it % 3) * SC_BSTAGE;
#pragma unroll
            for (int ks = 0; ks < 2; ks++) {
                uint32_t chunk = (uint32_t)ks * 2 + lchunk;
                uint32_t fa[4][4], fb[2][4];
#pragma unroll
                for (int mf = 0; mf < 4; mf++) {
                    uint32_t row = arowi + mf * 16;
                    uint32_t a = abase + row * ROWB + ((chunk ^ ((row >> 1) & 3)) << 4);
                    ldm_x4(fa[mf], a);
                }
#pragma unroll
                for (int nb = 0; nb < 2; nb++) {
                    uint32_t row = browi + nb * 16;
                    uint32_t b = bbase + row * ROWB + ((chunk ^ ((row >> 1) & 3)) << 4);
                    ldm_x4(fb[nb], b);
                }
#pragma unroll
                for (int mf = 0; mf < 4; mf++)
#pragma unroll
                    for (int nf = 0; nf < 4; nf++) {
                        int nb = nf >> 1, sel = nf & 1;
                        mma16816(acc[mf][nf], fa[mf], fb[nb][sel], fb[nb][2 + sel]);
                    }
            }
        }
        // ---- per-l-tile epilogue (register-only) ----
        if ((it & 3) == 3) {
            int t = it >> 2;
#pragma unroll
            for (int nf = 0; nf < 4; nf++) {
                int col = wn * 32 + nf * 8 + t2;
                float cs0 = 0.f, cs1 = 0.f;
#pragma unroll
                for (int mf = 0; mf < 4; mf++) {
                    int r0 = wm * 64 + mf * 16 + g;
#pragma unroll
                    for (int half = 0; half < 2; half++) {
                        int r = r0 + half * 8;
                        float v0 = exp2f(acc[mf][nf][half * 2 + 0] * SC_LOG2E);
                        float v1 = exp2f(acc[mf][nf][half * 2 + 1] * SC_LOG2E);
                        __half h0 = __float2half(v0);
                        __half h1 = __float2half(v1);
                        cs0 += __half2float(h0);
                        cs1 += __half2float(h1);
                        size_t o = (rb + r) * LTOT + (size_t)t * 128 + col;
                        *(__half2*)&g_P[o] = __halves2half2(h0, h1);
                        acc[mf][nf][half * 2 + 0] = 0.f;
                        acc[mf][nf][half * 2 + 1] = 0.f;
                    }
                }
#pragma unroll
                for (int off = 4; off < 32; off <<= 1) {
                    cs0 += __shfl_xor_sync(0xffffffffu, cs0, off);
                    cs1 += __shfl_xor_sync(0xffffffffu, cs1, off);
                }
                if (g == 0) {
                    atomicAdd(&g_sum[h * LTOT + t * 128 + col], cs0);
                    atomicAdd(&g_sum[h * LTOT + t * 128 + col + 1], cs1);
                }
            }
        }
    }
}

// ctx: P single x V single -> C single
__global__ void __launch_bounds__(256, 2) k_ctx() {
    extern __shared__ char sm[];
    int mt = blockIdx.x, h = blockIdx.y;
    float acc[4][4][4];
    size_t aoff = ((size_t)h * SQ + (size_t)mt * 128) * LTOT;
    size_t boff = (size_t)h * DK * LTOT;
    gemm_main(g_P + aoff, g_Vt + boff, LTOT, LTOT, LTOT / BKT, sm, acc);
    EPI_COORDS();
#pragma unroll
    for (int mf = 0; mf < 4; mf++)
#pragma unroll
        for (int nf = 0; nf < 4; nf++) {
            int col = wn * 32 + nf * 8 + t2;
            int r0 = wm * 64 + mf * 16 + g;
#pragma unroll
            for (int half = 0; half < 2; half++) {
                int r = r0 + half * 8;
                __half h0 = __float2half(acc[mf][nf][half * 2 + 0]);
                __half h1 = __float2half(acc[mf][nf][half * 2 + 1]);
                size_t o = (size_t)(mt * 128 + r) * DM + (size_t)h * DK + col;
                *(__half2*)&g_C[o] = __halves2half2(h0, h1);
            }
        }
}

// out: C single x Wo single
__global__ void __launch_bounds__(256, 2) k_out(const float* __restrict__ bo,
                                                float* __restrict__ out) {
    extern __shared__ char sm[];
    int nt = blockIdx.x, mt = blockIdx.y;
    float acc[4][4][4];
    gemm_main(g_C + (size_t)mt * 128 * DM, g_Wot + (size_t)nt * 128 * DM,
              DM, DM, DM / BKT, sm, acc);
    EPI_COORDS();
    const float* bop = bo + nt * 128;
#pragma unroll
    for (int mf = 0; mf < 4; mf++)
#pragma unroll
        for (int nf = 0; nf < 4; nf++) {
            int col = wn * 32 + nf * 8 + t2;
            float b0 = bop[col], b1 = bop[col + 1];
            int r0 = wm * 64 + mf * 16 + g;
#pragma unroll
            for (int half = 0; half < 2; half++) {
                int r = r0 + half * 8;
                float2 v;
                v.x = acc[mf][nf][half * 2 + 0] + b0;
                v.y = acc[mf][nf][half * 2 + 1] + b1;
                *(float2*)&out[(size_t)(mt * 128 + r) * DM + (size_t)nt * 128 + col] = v;
            }
        }
}

// ============================ prep kernels ============================
__global__ void prep_init(const float* __restrict__ bk, const float* __restrict__ bv) {
    int i = blockIdx.x * 256 + threadIdx.x;
    if (i < H * DK) { g_kn[i] = bk[i]; g_vn[i] = bv[i]; }
    g_sum[i] = 0.f;
}

__global__ void knv_part(const float* __restrict__ x,
                         const float* __restrict__ Wk, const float* __restrict__ Wv) {
    int h = blockIdx.x, b = blockIdx.y;
    int k = threadIdx.x;
    const float* xl = x + (size_t)(SQ - 1) * DM + b * 512;
    const float* wk = Wk + (size_t)h * DM * DK + (size_t)b * 512 * DK + k;
    const float* wv = Wv + (size_t)h * DM * DK + (size_t)b * 512 * DK + k;
    float aK = 0.f, aV = 0.f;
#pragma unroll 4
    for (int d = 0; d < 512; d++) {
        float xv = xl[d];
        aK += xv * wk[(size_t)d * DK];
        aV += xv * wv[(size_t)d * DK];
    }
    atomicAdd(&g_kn[h * DK + k], aK);
    atomicAdd(&g_vn[h * DK + k], aV);
}

__global__ void conv_x(const float* __restrict__ x) {
    size_t i = (size_t)blockIdx.x * 256 + threadIdx.x;
    g_X[i] = __float2half(x[i]);
}

__global__ void conv_keys(const float* __restrict__ kc, const int* __restrict__ posp) {
    size_t i = (size_t)blockIdx.x * 256 + threadIdx.x;
    int h = (int)(i / ((size_t)LTOT * DK));
    int rem = (int)(i % ((size_t)LTOT * DK));
    int l = rem / DK, dk = rem % DK;
    int pos = posp[0];
    float v = (l == pos) ? g_kn[h * DK + dk] : kc[((size_t)h * MAXSEQ + l) * DK + dk];
    g_K[i] = __float2half(v);
}

__global__ void tconv_wq(const float* __restrict__ W) {
    __shared__ float t[32][33];
    int h = blockIdx.z;
    int c0 = blockIdx.x * 32;
    int r0 = blockIdx.y * 32;
    int tx = threadIdx.x, ty = threadIdx.y;
    const float* in = W + (size_t)h * DM * DK;
#pragma unroll
    for (int i = 0; i < 32; i += 8)
        t[ty + i][tx] = in[(size_t)(r0 + ty + i) * DK + c0 + tx];
    __syncthreads();
    __half* oh = g_Wqt + (size_t)h * DK * DM;
#pragma unroll
    for (int i = 0; i < 32; i += 8) {
        float v = t[tx][ty + i];
        size_t o = (size_t)(c0 + ty + i) * DM + r0 + tx;
        oh[o] = __float2half(v);
    }
}

__global__ void tconv_wo(const float* __restrict__ W) {
    __shared__ float t[32][33];
    int c0 = blockIdx.x * 32;
    int r0 = blockIdx.y * 32;
    int tx = threadIdx.x, ty = threadIdx.y;
#pragma unroll
    for (int i = 0; i < 32; i += 8)
        t[ty + i][tx] = W[(size_t)(r0 + ty + i) * DM + c0 + tx];
    __syncthreads();
#pragma unroll
    for (int i = 0; i < 32; i += 8) {
        float v = t[tx][ty + i];
        size_t o = (size_t)(c0 + ty + i) * DM + r0 + tx;
        g_Wot[o] = __float2half(v);
    }
}

// unscaled V transpose (fp32): VtF[h, dk, l] = V[h, l, dk] (l==pos row from g_vn)
__global__ void tconv_v(const float* __restrict__ vc, const int* __restrict__ posp) {
    __shared__ float t[32][33];
    int h = blockIdx.z;
    int c0 = blockIdx.x * 32;   // dk
    int r0 = blockIdx.y * 32;   // l
    int tx = threadIdx.x, ty = threadIdx.y;
    int pos = posp[0];
#pragma unroll
    for (int i = 0; i < 32; i += 8) {
        int l = r0 + ty + i, dk = c0 + tx;
        t[ty + i][tx] = (l == pos) ? g_vn[h * DK + dk]
                                   : vc[((size_t)h * MAXSEQ + l) * DK + dk];
    }
    __syncthreads();
    float* oF = g_VtF + (size_t)h * DK * LTOT;
#pragma unroll
    for (int i = 0; i < 32; i += 8)
        oF[(size_t)(c0 + ty + i) * LTOT + r0 + tx] = t[tx][ty + i];
}

// Vt = fp16(VtF * 1/sum[l]) — light streaming pass on the critical path
__global__ void vt_scale() {
    size_t i = ((size_t)blockIdx.x * 256 + threadIdx.x) * 4;
    int h = (int)(i / ((size_t)DK * LTOT));
    int l = (int)(i % LTOT);
    float4 v = *(const float4*)&g_VtF[i];
    const float* s = &g_sum[h * LTOT + l];
    float i0 = 1.0f / s[0], i1 = 1.0f / s[1], i2 = 1.0f / s[2], i3 = 1.0f / s[3];
    *(__half2*)&g_Vt[i]     = __halves2half2(__float2half(v.x * i0), __float2half(v.y * i1));
    *(__half2*)&g_Vt[i + 2] = __halves2half2(__float2half(v.z * i2), __float2half(v.w * i3));
}

// ============================ launch ============================
extern "C" void kernel_launch(void* const* d_in, const int* in_sizes, int n_in,
                              void* d_out, int out_size) {
    const float* x   = (const float*)d_in[0];
    const float* kc  = (const float*)d_in[1];
    const float* vc  = (const float*)d_in[2];
    const float* Wq  = (const float*)d_in[3];
    const float* bq  = (const float*)d_in[4];
    const float* Wk  = (const float*)d_in[5];
    const float* bk  = (const float*)d_in[6];
    const float* Wv  = (const float*)d_in[7];
    const float* bv  = (const float*)d_in[8];
    const float* Wo  = (const float*)d_in[9];
    const float* bo  = (const float*)d_in[10];
    const int*   pos = (const int*)d_in[11];
    float* out = (float*)d_out;

    const int SM2 = STAGES * 2 * MATB;   // 49152
    cudaFuncSetAttribute(k_qproj,  cudaFuncAttributeMaxDynamicSharedMemorySize, SM2);
    cudaFuncSetAttribute(k_scores, cudaFuncAttributeMaxDynamicSharedMemorySize, SC_SMEM);
    cudaFuncSetAttribute(k_ctx,    cudaFuncAttributeMaxDynamicSharedMemorySize, SM2);
    cudaFuncSetAttribute(k_out,    cudaFuncAttributeMaxDynamicSharedMemorySize, SM2);

    // R11/R14 launch topology with tconv_vt split: unscaled transpose hidden on s1,
    // only the light scale pass (vt_scale) remains on the critical path.
    // Handles created fresh per call, intentionally not destroyed (see R11 note).
    cudaStream_t s1;
    cudaStreamCreate(&s1);
    cudaEvent_t eFork, eKeys, eVt, eWo;
    cudaEventCreateWithFlags(&eFork, cudaEventDisableTiming);
    cudaEventCreateWithFlags(&eKeys, cudaEventDisableTiming);
    cudaEventCreateWithFlags(&eVt,   cudaEventDisableTiming);
    cudaEventCreateWithFlags(&eWo,   cudaEventDisableTiming);

    cudaEventRecord(eFork, 0);
    cudaStreamWaitEvent(s1, eFork, 0);

    // main stream: conv_x -> tconv_wq -> k_qproj (k_qproj is 4th launch = ncu slot)
    conv_x<<<(SQ * DM) / 256, 256>>>(x);                                  // 1
    tconv_wq<<<dim3(DK / 32, DM / 32, H), dim3(32, 8)>>>(Wq);             // 2
    prep_init<<<(H * LTOT) / 256, 256, 0, s1>>>(bk, bv);                  // 3 (s1)
    k_qproj<<<dim3(H, SQ / 128), 256, SM2>>>(bq);                         // 4 <- profiled
    knv_part<<<dim3(H, 8), DK, 0, s1>>>(x, Wk, Wv);                       // 5 (s1)
    conv_keys<<<(H * LTOT * DK) / 256, 256, 0, s1>>>(kc, pos);            // 6 (s1)
    cudaEventRecord(eKeys, s1);
    tconv_v<<<dim3(DK / 32, LTOT / 32, H), dim3(32, 8), 0, s1>>>(vc, pos);// 7 (s1)
    cudaEventRecord(eVt, s1);
    tconv_wo<<<dim3(DM / 32, DM / 32), dim3(32, 8), 0, s1>>>(Wo);         // 8 (s1)
    cudaEventRecord(eWo, s1);

    cudaStreamWaitEvent(0, eKeys, 0);
    k_scores<<<dim3(SQ / 128, H), 256, SC_SMEM>>>();                      // 9
    cudaStreamWaitEvent(0, eVt, 0);
    vt_scale<<<(int)(((size_t)H * DK * LTOT) / 1024), 256>>>();           // 10
    k_ctx<<<dim3(SQ / 128, H), 256, SM2>>>();                             // 11
    cudaStreamWaitEvent(0, eWo, 0);
    k_out<<<dim3(DM / 128, SQ / 128), 256, SM2>>>(bo, out);               // 12
}

// round 17
// speedup vs baseline: 1.1218x; 1.0096x over previous
#include <cuda_runtime.h>
#include <cuda_fp16.h>
#include <math.h>
#include <cstdint>

#define H 32
#define DM 4096
#define DK 128
#define SQ 1024
#define LTOT 4096
#define MAXSEQ 8192
#define RSQRT_DK 0.08838834764831845f
// RSQRT_DK * log2(e): scores epilogue uses exp2f(x * SC_LOG2E) == exp(x * RSQRT_DK)
#define SC_LOG2E 0.1275260257039059f

// GEMM tiling: CTA 128x128, warp tile 64x32 (2x4 warps), BK=32, 3 stages, 2 CTAs/SM
// smem rows: 64B (32 fp16) with XOR swizzle (group ^= (row>>1)&3)
#define STAGES 3
#define BKT 32
#define ROWB 64
#define MATB (128 * ROWB)            // 8192 B per matrix tile (128 rows x 32 k)

// ============================ scratch (device globals) ============================
__device__ __align__(16) __half g_X[(size_t)SQ * DM];
__device__ __align__(16) __half g_Wqt[(size_t)H * DK * DM];
__device__ __align__(16) __half g_K[(size_t)H * LTOT * DK];
__device__ __align__(16) __half g_Q[(size_t)H * SQ * DK];
__device__ __align__(16) __half g_P[(size_t)H * SQ * LTOT];
__device__ __align__(16) float  g_VtF[(size_t)H * DK * LTOT];   // unscaled V^T (fp32)
__device__ __align__(16) __half g_Vt[(size_t)H * DK * LTOT];
__device__ __align__(16) __half g_C[(size_t)SQ * DM];
__device__ __align__(16) __half g_Wot[(size_t)DM * DM];
__device__ float g_sum[H * LTOT];
__device__ float g_kn[H * DK], g_vn[H * DK];

// ============================ helpers ============================
__device__ __forceinline__ uint32_t smem_to_u32(const void* p) {
    uint32_t a;
    asm("{ .reg .u64 t; cvta.to.shared.u64 t, %1; cvt.u32.u64 %0, t; }" : "=r"(a) : "l"(p));
    return a;
}

__device__ __forceinline__ void ldm_x4(uint32_t (&r)[4], uint32_t addr) {
    asm volatile("ldmatrix.sync.aligned.m8n8.x4.shared.b16 {%0,%1,%2,%3}, [%4];"
                 : "=r"(r[0]), "=r"(r[1]), "=r"(r[2]), "=r"(r[3]) : "r"(addr));
}

__device__ __forceinline__ void mma16816(float (&d)[4], const uint32_t (&a)[4],
                                         uint32_t b0, uint32_t b1) {
    asm volatile(
        "mma.sync.aligned.m16n8k16.row.col.f32.f16.f16.f32 "
        "{%0,%1,%2,%3}, {%4,%5,%6,%7}, {%8,%9}, {%0,%1,%2,%3};"
        : "+f"(d[0]), "+f"(d[1]), "+f"(d[2]), "+f"(d[3])
        : "r"(a[0]), "r"(a[1]), "r"(a[2]), "r"(a[3]), "r"(b0), "r"(b1));
}

__device__ __forceinline__ void cp16(uint32_t s, const void* g) {
    asm volatile("cp.async.ca.shared.global [%0], [%1], 16;" :: "r"(s), "l"(g));
}
#define CP_COMMIT() asm volatile("cp.async.commit_group;" ::: "memory")
#define CP_WAIT1()  asm volatile("cp.async.wait_group 1;" ::: "memory")

// ============================ GEMM mainloop (1-term fp16) ============================
// acc[4][4][4] += sum over K of A[m][k] * B[n][k]. CTA 128x128, warp tile 64x32.
__device__ __forceinline__ void gemm_main(
    const __half* __restrict__ A0, const __half* __restrict__ B0,
    int lda, int ldb, int ktiles, char* sm, float (&acc)[4][4][4])
{
    constexpr int STAGEB = 2 * MATB;
    const int tid = threadIdx.x;
    const int wid = tid >> 5, lane = tid & 31;
    const int wm = wid >> 2, wn = wid & 3;
    uint32_t smb = smem_to_u32(sm);

#pragma unroll
    for (int mf = 0; mf < 4; mf++)
#pragma unroll
        for (int nf = 0; nf < 4; nf++)
#pragma unroll
            for (int i = 0; i < 4; i++) acc[mf][nf][i] = 0.f;

    auto load_stage = [&](int slot, int c) {
#pragma unroll
        for (int j = 0; j < 4; j++) {
            int i = tid + j * 256;
            int mat = i >> 9;
            int rem = i & 511;
            int row = rem >> 2, c4 = rem & 3;
            const __half* src = mat ? B0 : A0;
            int ld = mat ? ldb : lda;
            const void* g = src + (size_t)row * ld + (size_t)c * BKT + c4 * 8;
            uint32_t sw = (uint32_t)(c4 ^ ((row >> 1) & 3));
            uint32_t s = smb + slot * STAGEB + mat * MATB + row * ROWB + sw * 16;
            cp16(s, g);
        }
        CP_COMMIT();
    };

    const uint32_t lrow = (uint32_t)(lane & 15);
    const uint32_t lchunk = (uint32_t)((lane >> 4) & 1);
    const uint32_t arowi = (uint32_t)(wm * 64) + lrow;
    const uint32_t browi = (uint32_t)(wn * 32) + lrow;

    auto compute = [&](int slot) {
        uint32_t base = smb + slot * STAGEB;
#pragma unroll
        for (int ks = 0; ks < 2; ks++) {
            uint32_t chunk = (uint32_t)ks * 2 + lchunk;
            uint32_t fa[4][4], fb[2][4];
#pragma unroll
            for (int mf = 0; mf < 4; mf++) {
                uint32_t row = arowi + mf * 16;
                uint32_t a = base + row * ROWB + ((chunk ^ ((row >> 1) & 3)) << 4);
                ldm_x4(fa[mf], a);
            }
#pragma unroll
            for (int nb = 0; nb < 2; nb++) {
                uint32_t row = browi + nb * 16;
                uint32_t b = base + MATB + row * ROWB + ((chunk ^ ((row >> 1) & 3)) << 4);
                ldm_x4(fb[nb], b);
            }
#pragma unroll
            for (int mf = 0; mf < 4; mf++)
#pragma unroll
                for (int nf = 0; nf < 4; nf++) {
                    int nb = nf >> 1, sel = nf & 1;
                    mma16816(acc[mf][nf], fa[mf], fb[nb][sel], fb[nb][2 + sel]);
                }
        }
    };

    load_stage(0, 0);
    if (ktiles > 1) load_stage(1, 1);
    else CP_COMMIT();
#pragma unroll 1
    for (int c = 0; c < ktiles; c++) {
        CP_WAIT1();
        __syncthreads();
        if (c + 2 < ktiles) load_stage((c + 2) % 3, c + 2);
        else CP_COMMIT();
        compute(c % 3);
    }
}

#define EPI_COORDS() \
    const int tid = threadIdx.x; \
    const int wid = tid >> 5, lane = tid & 31; \
    const int wm = wid >> 2, wn = wid & 3; \
    const int g = lane >> 2, t2 = (lane & 3) * 2;

// ============================ GEMM kernels ============================
// qproj: X single x Wq single -> Q single
__global__ void __launch_bounds__(256, 2) k_qproj(const float* __restrict__ bq) {
    extern __shared__ char sm[];
    int h = blockIdx.x, mt = blockIdx.y;
    float acc[4][4][4];
    gemm_main(g_X + (size_t)mt * 128 * DM, g_Wqt + (size_t)h * DK * DM,
              DM, DM, DM / BKT, sm, acc);
    EPI_COORDS();
    const float* bqp = bq + h * DK;
    size_t rb = (size_t)h * SQ + (size_t)mt * 128;
#pragma unroll
    for (int mf = 0; mf < 4; mf++)
#pragma unroll
        for (int nf = 0; nf < 4; nf++) {
            int col = wn * 32 + nf * 8 + t2;
            float b0 = bqp[col], b1 = bqp[col + 1];
            int r0 = wm * 64 + mf * 16 + g;
#pragma unroll
            for (int half = 0; half < 2; half++) {
                int r = r0 + half * 8;
                __half h0 = __float2half(acc[mf][nf][half * 2 + 0] + b0);
                __half h1 = __float2half(acc[mf][nf][half * 2 + 1] + b1);
                size_t o = (rb + r) * DK + col;
                *(__half2*)&g_Q[o] = __halves2half2(h0, h1);
            }
        }
}

// ======================= scores: persistent-Q streaming kernel =======================
#define SC_A_BYTES 32768                      // Q single: 4 chunk-blocks x MATB
#define SC_BSTAGE  8192                       // K single: 1 mat x MATB
#define SC_SMEM (SC_A_BYTES + 3 * SC_BSTAGE)  // 57344

__global__ void __launch_bounds__(256, 2) k_scores() {
    extern __shared__ char sm[];
    const int tid = threadIdx.x;
    const int wid = tid >> 5, lane = tid & 31;
    const int wm = wid >> 2, wn = wid & 3;
    const int g = lane >> 2, t2 = (lane & 3) * 2;
    int mt = blockIdx.x, h = blockIdx.y;
    uint32_t smb = smem_to_u32(sm);
    uint32_t smA = smb;
    uint32_t smB = smb + SC_A_BYTES;

    // ---- load persistent Q tile: 2048 x 16B ----
    {
        const __half* src = g_Q + ((size_t)h * SQ + (size_t)mt * 128) * DK;
#pragma unroll
        for (int j = 0; j < 8; j++) {
            int i = tid + j * 256;
            int row = i >> 4, grp = i & 15;
            int cg = grp >> 2, c4 = grp & 3;
            const void* gp = src + (size_t)row * DK + grp * 8;
            uint32_t sw = (uint32_t)(c4 ^ ((row >> 1) & 3));
            uint32_t s = smA + cg * 8192 + row * ROWB + sw * 16;
            cp16(s, gp);
        }
        CP_COMMIT();
    }

    const __half* B0 = g_K + (size_t)h * LTOT * DK;
    auto load_B = [&](int slot, int it) {
        int t = it >> 2, cc = it & 3;
#pragma unroll
        for (int j = 0; j < 2; j++) {
            int i = tid + j * 256;
            int row = i >> 2, c4 = i & 3;
            const void* gp = B0 + (size_t)(t * 128 + row) * DK + cc * BKT + c4 * 8;
            uint32_t sw = (uint32_t)(c4 ^ ((row >> 1) & 3));
            uint32_t s = smB + slot * SC_BSTAGE + row * ROWB + sw * 16;
            cp16(s, gp);
        }
        CP_COMMIT();
    };

    const uint32_t lrow = (uint32_t)(lane & 15);
    const uint32_t lchunk = (uint32_t)((lane >> 4) & 1);
    const uint32_t arowi = (uint32_t)(wm * 64) + lrow;
    const uint32_t browi = (uint32_t)(wn * 32) + lrow;

    float acc[4][4][4];
#pragma unroll
    for (int mf = 0; mf < 4; mf++)
#pragma unroll
        for (int nf = 0; nf < 4; nf++)
#pragma unroll
            for (int i = 0; i < 4; i++) acc[mf][nf][i] = 0.f;

    load_B(0, 0);
    load_B(1, 1);
    size_t rb = (size_t)h * SQ + (size_t)mt * 128;

#pragma unroll 1
    for (int it = 0; it < 128; it++) {
        CP_WAIT1();
        __syncthreads();
        if (it + 2 < 128) load_B((it + 2) % 3, it + 2);
        else CP_COMMIT();
        {
            uint32_t abase = smA + (uint32_t)(it & 3) * 8192;
            uint32_t bbase = smB + (uint32_t)(it % 3) * SC_BSTAGE;
#pragma unroll
            for (int ks = 0; ks < 2; ks++) {
                uint32_t chunk = (uint32_t)ks * 2 + lchunk;
                uint32_t fa[4][4], fb[2][4];
#pragma unroll
                for (int mf = 0; mf < 4; mf++) {
                    uint32_t row = arowi + mf * 16;
                    uint32_t a = abase + row * ROWB + ((chunk ^ ((row >> 1) & 3)) << 4);
                    ldm_x4(fa[mf], a);
                }
#pragma unroll
                for (int nb = 0; nb < 2; nb++) {
                    uint32_t row = browi + nb * 16;
                    uint32_t b = bbase + row * ROWB + ((chunk ^ ((row >> 1) & 3)) << 4);
                    ldm_x4(fb[nb], b);
                }
#pragma unroll
                for (int mf = 0; mf < 4; mf++)
#pragma unroll
                    for (int nf = 0; nf < 4; nf++) {
                        int nb = nf >> 1, sel = nf & 1;
                        mma16816(acc[mf][nf], fa[mf], fb[nb][sel], fb[nb][2 + sel]);
                    }
            }
        }
        // ---- per-l-tile epilogue (register-only) ----
        if ((it & 3) == 3) {
            int t = it >> 2;
#pragma unroll
            for (int nf = 0; nf < 4; nf++) {
                int col = wn * 32 + nf * 8 + t2;
                float cs0 = 0.f, cs1 = 0.f;
#pragma unroll
                for (int mf = 0; mf < 4; mf++) {
                    int r0 = wm * 64 + mf * 16 + g;
#pragma unroll
                    for (int half = 0; half < 2; half++) {
                        int r = r0 + half * 8;
                        float v0 = exp2f(acc[mf][nf][half * 2 + 0] * SC_LOG2E);
                        float v1 = exp2f(acc[mf][nf][half * 2 + 1] * SC_LOG2E);
                        __half h0 = __float2half(v0);
                        __half h1 = __float2half(v1);
                        cs0 += __half2float(h0);
                        cs1 += __half2float(h1);
                        size_t o = (rb + r) * LTOT + (size_t)t * 128 + col;
                        *(__half2*)&g_P[o] = __halves2half2(h0, h1);
                        acc[mf][nf][half * 2 + 0] = 0.f;
                        acc[mf][nf][half * 2 + 1] = 0.f;
                    }
                }
#pragma unroll
                for (int off = 4; off < 32; off <<= 1) {
                    cs0 += __shfl_xor_sync(0xffffffffu, cs0, off);
                    cs1 += __shfl_xor_sync(0xffffffffu, cs1, off);
                }
                if (g == 0) {
                    atomicAdd(&g_sum[h * LTOT + t * 128 + col], cs0);
                    atomicAdd(&g_sum[h * LTOT + t * 128 + col + 1], cs1);
                }
            }
        }
    }
}

// ctx: P single x V single -> C single
__global__ void __launch_bounds__(256, 2) k_ctx() {
    extern __shared__ char sm[];
    int mt = blockIdx.x, h = blockIdx.y;
    float acc[4][4][4];
    size_t aoff = ((size_t)h * SQ + (size_t)mt * 128) * LTOT;
    size_t boff = (size_t)h * DK * LTOT;
    gemm_main(g_P + aoff, g_Vt + boff, LTOT, LTOT, LTOT / BKT, sm, acc);
    EPI_COORDS();
#pragma unroll
    for (int mf = 0; mf < 4; mf++)
#pragma unroll
        for (int nf = 0; nf < 4; nf++) {
            int col = wn * 32 + nf * 8 + t2;
            int r0 = wm * 64 + mf * 16 + g;
#pragma unroll
            for (int half = 0; half < 2; half++) {
                int r = r0 + half * 8;
                __half h0 = __float2half(acc[mf][nf][half * 2 + 0]);
                __half h1 = __float2half(acc[mf][nf][half * 2 + 1]);
                size_t o = (size_t)(mt * 128 + r) * DM + (size_t)h * DK + col;
                *(__half2*)&g_C[o] = __halves2half2(h0, h1);
            }
        }
}

// out: C single x Wo single
__global__ void __launch_bounds__(256, 2) k_out(const float* __restrict__ bo,
                                                float* __restrict__ out) {
    extern __shared__ char sm[];
    int nt = blockIdx.x, mt = blockIdx.y;
    float acc[4][4][4];
    gemm_main(g_C + (size_t)mt * 128 * DM, g_Wot + (size_t)nt * 128 * DM,
              DM, DM, DM / BKT, sm, acc);
    EPI_COORDS();
    const float* bop = bo + nt * 128;
#pragma unroll
    for (int mf = 0; mf < 4; mf++)
#pragma unroll
        for (int nf = 0; nf < 4; nf++) {
            int col = wn * 32 + nf * 8 + t2;
            float b0 = bop[col], b1 = bop[col + 1];
            int r0 = wm * 64 + mf * 16 + g;
#pragma unroll
            for (int half = 0; half < 2; half++) {
                int r = r0 + half * 8;
                float2 v;
                v.x = acc[mf][nf][half * 2 + 0] + b0;
                v.y = acc[mf][nf][half * 2 + 1] + b1;
                *(float2*)&out[(size_t)(mt * 128 + r) * DM + (size_t)nt * 128 + col] = v;
            }
        }
}

// ============================ prep kernels ============================
__global__ void prep_init(const float* __restrict__ bk, const float* __restrict__ bv) {
    int i = blockIdx.x * 256 + threadIdx.x;
    if (i < H * DK) { g_kn[i] = bk[i]; g_vn[i] = bv[i]; }
    g_sum[i] = 0.f;
}

__global__ void knv_part(const float* __restrict__ x,
                         const float* __restrict__ Wk, const float* __restrict__ Wv) {
    int h = blockIdx.x, b = blockIdx.y;
    int k = threadIdx.x;
    const float* xl = x + (size_t)(SQ - 1) * DM + b * 512;
    const float* wk = Wk + (size_t)h * DM * DK + (size_t)b * 512 * DK + k;
    const float* wv = Wv + (size_t)h * DM * DK + (size_t)b * 512 * DK + k;
    float aK = 0.f, aV = 0.f;
#pragma unroll 4
    for (int d = 0; d < 512; d++) {
        float xv = xl[d];
        aK += xv * wk[(size_t)d * DK];
        aV += xv * wv[(size_t)d * DK];
    }
    atomicAdd(&g_kn[h * DK + k], aK);
    atomicAdd(&g_vn[h * DK + k], aV);
}

__global__ void conv_x(const float* __restrict__ x) {
    size_t i = (size_t)blockIdx.x * 256 + threadIdx.x;
    g_X[i] = __float2half(x[i]);
}

__global__ void conv_keys(const float* __restrict__ kc, const int* __restrict__ posp) {
    size_t i = (size_t)blockIdx.x * 256 + threadIdx.x;
    int h = (int)(i / ((size_t)LTOT * DK));
    int rem = (int)(i % ((size_t)LTOT * DK));
    int l = rem / DK, dk = rem % DK;
    int pos = posp[0];
    float v = (l == pos) ? g_kn[h * DK + dk] : kc[((size_t)h * MAXSEQ + l) * DK + dk];
    g_K[i] = __float2half(v);
}

__global__ void tconv_wq(const float* __restrict__ W) {
    __shared__ float t[32][33];
    int h = blockIdx.z;
    int c0 = blockIdx.x * 32;
    int r0 = blockIdx.y * 32;
    int tx = threadIdx.x, ty = threadIdx.y;
    const float* in = W + (size_t)h * DM * DK;
#pragma unroll
    for (int i = 0; i < 32; i += 8)
        t[ty + i][tx] = in[(size_t)(r0 + ty + i) * DK + c0 + tx];
    __syncthreads();
    __half* oh = g_Wqt + (size_t)h * DK * DM;
#pragma unroll
    for (int i = 0; i < 32; i += 8) {
        float v = t[tx][ty + i];
        size_t o = (size_t)(c0 + ty + i) * DM + r0 + tx;
        oh[o] = __float2half(v);
    }
}

__global__ void tconv_wo(const float* __restrict__ W) {
    __shared__ float t[32][33];
    int c0 = blockIdx.x * 32;
    int r0 = blockIdx.y * 32;
    int tx = threadIdx.x, ty = threadIdx.y;
#pragma unroll
    for (int i = 0; i < 32; i += 8)
        t[ty + i][tx] = W[(size_t)(r0 + ty + i) * DM + c0 + tx];
    __syncthreads();
#pragma unroll
    for (int i = 0; i < 32; i += 8) {
        float v = t[tx][ty + i];
        size_t o = (size_t)(c0 + ty + i) * DM + r0 + tx;
        g_Wot[o] = __float2half(v);
    }
}

// unscaled V transpose (fp32): VtF[h, dk, l] = V[h, l, dk] (l==pos row from g_vn)
__global__ void tconv_v(const float* __restrict__ vc, const int* __restrict__ posp) {
    __shared__ float t[32][33];
    int h = blockIdx.z;
    int c0 = blockIdx.x * 32;   // dk
    int r0 = blockIdx.y * 32;   // l
    int tx = threadIdx.x, ty = threadIdx.y;
    int pos = posp[0];
#pragma unroll
    for (int i = 0; i < 32; i += 8) {
        int l = r0 + ty + i, dk = c0 + tx;
        t[ty + i][tx] = (l == pos) ? g_vn[h * DK + dk]
                                   : vc[((size_t)h * MAXSEQ + l) * DK + dk];
    }
    __syncthreads();
    float* oF = g_VtF + (size_t)h * DK * LTOT;
#pragma unroll
    for (int i = 0; i < 32; i += 8)
        oF[(size_t)(c0 + ty + i) * LTOT + r0 + tx] = t[tx][ty + i];
}

// Vt = fp16(VtF * 1/sum[l]) — light streaming pass on the critical path
__global__ void vt_scale() {
    size_t i = ((size_t)blockIdx.x * 256 + threadIdx.x) * 4;
    int h = (int)(i / ((size_t)DK * LTOT));
    int l = (int)(i % LTOT);
    float4 v = *(const float4*)&g_VtF[i];
    const float* s = &g_sum[h * LTOT + l];
    float i0 = 1.0f / s[0], i1 = 1.0f / s[1], i2 = 1.0f / s[2], i3 = 1.0f / s[3];
    *(__half2*)&g_Vt[i]     = __halves2half2(__float2half(v.x * i0), __float2half(v.y * i1));
    *(__half2*)&g_Vt[i + 2] = __halves2half2(__float2half(v.z * i2), __float2half(v.w * i3));
}

// ============================ launch ============================
extern "C" void kernel_launch(void* const* d_in, const int* in_sizes, int n_in,
                              void* d_out, int out_size) {
    const float* x   = (const float*)d_in[0];
    const float* kc  = (const float*)d_in[1];
    const float* vc  = (const float*)d_in[2];
    const float* Wq  = (const float*)d_in[3];
    const float* bq  = (const float*)d_in[4];
    const float* Wk  = (const float*)d_in[5];
    const float* bk  = (const float*)d_in[6];
    const float* Wv  = (const float*)d_in[7];
    const float* bv  = (const float*)d_in[8];
    const float* Wo  = (const float*)d_in[9];
    const float* bo  = (const float*)d_in[10];
    const int*   pos = (const int*)d_in[11];
    float* out = (float*)d_out;

    const int SM2 = STAGES * 2 * MATB;   // 49152
    cudaFuncSetAttribute(k_qproj,  cudaFuncAttributeMaxDynamicSharedMemorySize, SM2);
    cudaFuncSetAttribute(k_scores, cudaFuncAttributeMaxDynamicSharedMemorySize, SC_SMEM);
    cudaFuncSetAttribute(k_ctx,    cudaFuncAttributeMaxDynamicSharedMemorySize, SM2);
    cudaFuncSetAttribute(k_out,    cudaFuncAttributeMaxDynamicSharedMemorySize, SM2);

    // R15 topology, but tconv_wq moved to the HEAD of s1 so it co-runs with
    // conv_x on main (the R16 overlap) using only the two streams that pass
    // the allocation guard. Handles created fresh per call, not destroyed
    // (destroying a capture-participating stream mid-capture is invalid).
    cudaStream_t s1;
    cudaStreamCreate(&s1);
    cudaEvent_t eFork, eWq, eKeys, eVt, eWo;
    cudaEventCreateWithFlags(&eFork, cudaEventDisableTiming);
    cudaEventCreateWithFlags(&eWq,   cudaEventDisableTiming);
    cudaEventCreateWithFlags(&eKeys, cudaEventDisableTiming);
    cudaEventCreateWithFlags(&eVt,   cudaEventDisableTiming);
    cudaEventCreateWithFlags(&eWo,   cudaEventDisableTiming);

    cudaEventRecord(eFork, 0);
    cudaStreamWaitEvent(s1, eFork, 0);

    // main: conv_x -> (wait eWq) -> k_qproj (k_qproj = global launch #4, ncu slot)
    conv_x<<<(SQ * DM) / 256, 256>>>(x);                                  // 1
    tconv_wq<<<dim3(DK / 32, DM / 32, H), dim3(32, 8), 0, s1>>>(Wq);      // 2 (s1)
    cudaEventRecord(eWq, s1);
    prep_init<<<(H * LTOT) / 256, 256, 0, s1>>>(bk, bv);                  // 3 (s1)
    cudaStreamWaitEvent(0, eWq, 0);
    k_qproj<<<dim3(H, SQ / 128), 256, SM2>>>(bq);                         // 4 <- profiled
    knv_part<<<dim3(H, 8), DK, 0, s1>>>(x, Wk, Wv);                       // 5 (s1)
    conv_keys<<<(H * LTOT * DK) / 256, 256, 0, s1>>>(kc, pos);            // 6 (s1)
    cudaEventRecord(eKeys, s1);
    tconv_v<<<dim3(DK / 32, LTOT / 32, H), dim3(32, 8), 0, s1>>>(vc, pos);// 7 (s1)
    cudaEventRecord(eVt, s1);
    tconv_wo<<<dim3(DM / 32, DM / 32), dim3(32, 8), 0, s1>>>(Wo);         // 8 (s1)
    cudaEventRecord(eWo, s1);

    cudaStreamWaitEvent(0, eKeys, 0);
    k_scores<<<dim3(SQ / 128, H), 256, SC_SMEM>>>();                      // 9
    cudaStreamWaitEvent(0, eVt, 0);
    vt_scale<<<(int)(((size_t)H * DK * LTOT) / 1024), 256>>>();           // 10
    k_ctx<<<dim3(SQ / 128, H), 256, SM2>>>();                             // 11
    cudaStreamWaitEvent(0, eWo, 0);
    k_out<<<dim3(DM / 128, SQ / 128), 256, SM2>>>(bo, out);               // 12
}